// round 9
// baseline (speedup 1.0000x reference)
#include <cuda_runtime.h>
#include <cuda_fp16.h>

#define NN 100000
#define NE 1600000
#define CAP 128
#define NF1 128
#define NH  64
#define NC  40

typedef unsigned long long ull;

// -------- scratch (device globals; no allocation allowed) --------
__device__ float  g_deg[NN];
__device__ float  g_dinv[NN];
__device__ int    g_cnt[NN];
__device__ int2   g_slot[(long long)NN * CAP];  // (src_row, float_bits(raw w)); zero-init -> row 0 safe
__device__ __half g_h1h[(long long)NN * NH];    // fp16(x @ W1)
__device__ __half g_h2h[(long long)NN * NC];    // fp16(out1 @ W2)

// -------- packed f32x2 helpers --------
__device__ __forceinline__ ull pack2(float x, float y) {
    ull r;
    asm("mov.b64 %0, {%1, %2};" : "=l"(r) : "f"(x), "f"(y));
    return r;
}
__device__ __forceinline__ void fma2(ull& d, ull a, ull b) {
    asm("fma.rn.f32x2 %0, %1, %2, %0;" : "+l"(d) : "l"(a), "l"(b));
}
__device__ __forceinline__ float2 unpack2(ull v) {
    float2 f;
    asm("mov.b64 {%0, %1}, %2;" : "=f"(f.x), "=f"(f.y) : "l"(v));
    return f;
}

// -------- prep kernels --------
__global__ void k_initdeg() {
    int n = blockIdx.x * blockDim.x + threadIdx.x;
    if (n < NN) g_deg[n] = 1.0f;   // self-loop weight 1
}

__global__ void k_deg(const int* __restrict__ ei, const float* __restrict__ ew) {
    int e = blockIdx.x * blockDim.x + threadIdx.x;
    if (e < NE) {
        int c = ei[NE + e];
        if (c >= 0 && c < NN) atomicAdd(&g_deg[c], ew[e]);
    }
}

__global__ void k_dinv() {
    int n = blockIdx.x * blockDim.x + threadIdx.x;
    if (n < NN) {
        float d = g_deg[n];
        g_dinv[n] = d > 0.f ? rsqrtf(d) : 0.f;
    }
}

// Slot placement with RAW weight (no deg dependency) -> runs concurrent with k_deg.
__global__ void k_place_raw(const int* __restrict__ ei, const float* __restrict__ ew) {
    int e = blockIdx.x * blockDim.x + threadIdx.x;
    if (e >= NE) return;
    int r = ei[e];
    int c = ei[NE + e];
    if (r < 0 || r >= NN || c < 0 || c >= NN) return;
    int pos = atomicAdd(&g_cnt[c], 1);
    if (pos < CAP) {
        int2 s;
        s.x = r;
        s.y = __float_as_int(ew[e]);
        g_slot[(long long)c * CAP + pos] = s;
    }
}

// -------- one 8-slot masked gather group (dinv applied at gather time) --------
template<int STRIDE>
__device__ __forceinline__ void gather_group(const int2* __restrict__ slots, int kk, int c,
                                             const __half* __restrict__ h,
                                             const float* __restrict__ dinv,
                                             int lane, float2& acc) {
    int4 sa = *(const int4*)&slots[kk];
    int4 sb = *(const int4*)&slots[kk + 2];
    int4 sc = *(const int4*)&slots[kk + 4];
    int4 sd = *(const int4*)&slots[kk + 6];
    float d0 = dinv[sa.x], d1 = dinv[sa.z], d2 = dinv[sb.x], d3 = dinv[sb.z];
    float d4 = dinv[sc.x], d5 = dinv[sc.z], d6 = dinv[sd.x], d7 = dinv[sd.z];
    __half2 v0 = *(const __half2*)&h[(long long)sa.x * STRIDE + lane * 2];
    __half2 v1 = *(const __half2*)&h[(long long)sa.z * STRIDE + lane * 2];
    __half2 v2 = *(const __half2*)&h[(long long)sb.x * STRIDE + lane * 2];
    __half2 v3 = *(const __half2*)&h[(long long)sb.z * STRIDE + lane * 2];
    __half2 v4 = *(const __half2*)&h[(long long)sc.x * STRIDE + lane * 2];
    __half2 v5 = *(const __half2*)&h[(long long)sc.z * STRIDE + lane * 2];
    __half2 v6 = *(const __half2*)&h[(long long)sd.x * STRIDE + lane * 2];
    __half2 v7 = *(const __half2*)&h[(long long)sd.z * STRIDE + lane * 2];
    float n0 = (kk + 0 < c) ? __int_as_float(sa.y) * d0 : 0.f;
    float n1 = (kk + 1 < c) ? __int_as_float(sa.w) * d1 : 0.f;
    float n2 = (kk + 2 < c) ? __int_as_float(sb.y) * d2 : 0.f;
    float n3 = (kk + 3 < c) ? __int_as_float(sb.w) * d3 : 0.f;
    float n4 = (kk + 4 < c) ? __int_as_float(sc.y) * d4 : 0.f;
    float n5 = (kk + 5 < c) ? __int_as_float(sc.w) * d5 : 0.f;
    float n6 = (kk + 6 < c) ? __int_as_float(sd.y) * d6 : 0.f;
    float n7 = (kk + 7 < c) ? __int_as_float(sd.w) * d7 : 0.f;
    float2 f0 = __half22float2(v0), f1 = __half22float2(v1);
    float2 f2 = __half22float2(v2), f3 = __half22float2(v3);
    float2 f4 = __half22float2(v4), f5 = __half22float2(v5);
    float2 f6 = __half22float2(v6), f7 = __half22float2(v7);
    acc.x = fmaf(n0, f0.x, acc.x); acc.y = fmaf(n0, f0.y, acc.y);
    acc.x = fmaf(n1, f1.x, acc.x); acc.y = fmaf(n1, f1.y, acc.y);
    acc.x = fmaf(n2, f2.x, acc.x); acc.y = fmaf(n2, f2.y, acc.y);
    acc.x = fmaf(n3, f3.x, acc.x); acc.y = fmaf(n3, f3.y, acc.y);
    acc.x = fmaf(n4, f4.x, acc.x); acc.y = fmaf(n4, f4.y, acc.y);
    acc.x = fmaf(n5, f5.x, acc.x); acc.y = fmaf(n5, f5.y, acc.y);
    acc.x = fmaf(n6, f6.x, acc.x); acc.y = fmaf(n6, f6.y, acc.y);
    acc.x = fmaf(n7, f7.x, acc.x); acc.y = fmaf(n7, f7.y, acc.y);
}

// -------- GEMM1: g_h1h[N,64] = fp16(x[N,128] @ W1[128,64]) --------
__global__ void gemm1(const float* __restrict__ A, const float* __restrict__ B) {
    __shared__ __align__(16) float sA[64][68];
    __shared__ __align__(16) float sB[64][64];
    int tid = threadIdx.x;
    int tx = tid & 15, ty = tid >> 4;
    int row0 = blockIdx.x * 64;
    ull acc2[4][2] = {};

    for (int kc = 0; kc < 2; kc++) {
#pragma unroll
        for (int t = 0; t < 4; t++) {
            int lin = (t * 256 + tid) * 4;
            int r  = lin >> 6;
            int k0 = lin & 63;
            int grow = row0 + r;
            float4 v = make_float4(0.f, 0.f, 0.f, 0.f);
            if (grow < NN) v = *(const float4*)&A[(long long)grow * NF1 + kc * 64 + k0];
            *(float4*)&sA[r][k0] = v;
            float4 w = *(const float4*)&B[(kc * 64 + r) * NH + k0];
            *(float4*)&sB[r][k0] = w;
        }
        __syncthreads();
#pragma unroll
        for (int k = 0; k < 64; k++) {
            const ull* bp = (const ull*)&sB[k][tx * 4];
            ull b01 = bp[0];
            ull b23 = bp[1];
#pragma unroll
            for (int i = 0; i < 4; i++) {
                float a = sA[ty * 4 + i][k];
                ull pa = pack2(a, a);
                fma2(acc2[i][0], pa, b01);
                fma2(acc2[i][1], pa, b23);
            }
        }
        __syncthreads();
    }
#pragma unroll
    for (int i = 0; i < 4; i++) {
        int grow = row0 + ty * 4 + i;
        if (grow < NN) {
            __half2 h0 = __float22half2_rn(unpack2(acc2[i][0]));
            __half2 h1 = __float22half2_rn(unpack2(acc2[i][1]));
            uint2 st;
            st.x = *(unsigned*)&h0;
            st.y = *(unsigned*)&h1;
            *(uint2*)&g_h1h[(long long)grow * NH + tx * 4] = st;
        }
    }
}

// -------- FUSED gather1 + GEMM2, 2-node-interleaved gather --------
__global__ void g1g2(const float* __restrict__ b1, const float* __restrict__ W2) {
    __shared__ __align__(16) float sA[64][68];    // out1 rows (fp32)
    __shared__ __align__(16) float sB[64 * 40];   // W2
    int tid = threadIdx.x;          // 0..255
    int warp = tid >> 5, lane = tid & 31;
    int row0 = blockIdx.x * 64;

    for (int idx = tid; idx < 64 * 40; idx += 256) sB[idx] = W2[idx];

    float bx = __ldg(&b1[lane * 2]);
    float by = __ldg(&b1[lane * 2 + 1]);

#pragma unroll
    for (int p = 0; p < 4; p++) {
        int rA = warp * 8 + p * 2;
        int nA = row0 + rA;
        int nB = nA + 1;
        bool okA = nA < NN, okB = nB < NN;
        float2 aA = make_float2(0.f, 0.f), aB = make_float2(0.f, 0.f);
        int cA = okA ? min(g_cnt[nA], CAP) : 0;
        int cB = okB ? min(g_cnt[nB], CAP) : 0;
        const int2* sltA = &g_slot[(long long)nA * CAP];
        const int2* sltB = &g_slot[(long long)nB * CAP];
        int cmax = max(cA, cB);
        for (int kk = 0; kk < cmax; kk += 8) {
            if (kk < cA) gather_group<NH>(sltA, kk, cA, g_h1h, g_dinv, lane, aA);
            if (kk < cB) gather_group<NH>(sltB, kk, cB, g_h1h, g_dinv, lane, aB);
        }
        float2 oA = make_float2(0.f, 0.f), oB = make_float2(0.f, 0.f);
        if (okA) {
            float dc = g_dinv[nA];
            float2 self = __half22float2(*(const __half2*)&g_h1h[(long long)nA * NH + lane * 2]);
            oA.x = fmaxf(fmaf(dc, fmaf(dc, self.x, aA.x), bx), 0.f);
            oA.y = fmaxf(fmaf(dc, fmaf(dc, self.y, aA.y), by), 0.f);
        }
        if (okB) {
            float dc = g_dinv[nB];
            float2 self = __half22float2(*(const __half2*)&g_h1h[(long long)nB * NH + lane * 2]);
            oB.x = fmaxf(fmaf(dc, fmaf(dc, self.x, aB.x), bx), 0.f);
            oB.y = fmaxf(fmaf(dc, fmaf(dc, self.y, aB.y), by), 0.f);
        }
        *(float2*)&sA[rA][lane * 2] = oA;
        *(float2*)&sA[rA + 1][lane * 2] = oB;
    }
    __syncthreads();

    if (tid < 160) {
        int tx = tid % 10, ty = tid / 10;
        ull acc2[4][2] = {};
#pragma unroll
        for (int k = 0; k < 64; k++) {
            const ull* bp = (const ull*)&sB[k * 40 + tx * 4];
            ull b01 = bp[0];
            ull b23 = bp[1];
#pragma unroll
            for (int i = 0; i < 4; i++) {
                float a = sA[ty * 4 + i][k];
                ull pa = pack2(a, a);
                fma2(acc2[i][0], pa, b01);
                fma2(acc2[i][1], pa, b23);
            }
        }
#pragma unroll
        for (int i = 0; i < 4; i++) {
            int grow = row0 + ty * 4 + i;
            if (grow < NN) {
                __half2 h0 = __float22half2_rn(unpack2(acc2[i][0]));
                __half2 h1 = __float22half2_rn(unpack2(acc2[i][1]));
                uint2 st;
                st.x = *(unsigned*)&h0;
                st.y = *(unsigned*)&h1;
                *(uint2*)&g_h2h[(long long)grow * NC + tx * 4] = st;
            }
        }
    }
}

// -------- gather layer 2: warp per 2 nodes, lanes 0..19 --------
__global__ void gather2(const float* __restrict__ b2, float* __restrict__ out) {
    int warp = blockIdx.x * 8 + (threadIdx.x >> 5);
    int nA = warp * 2;
    int nB = nA + 1;
    if (nA >= NN) return;
    int lane = threadIdx.x & 31;
    if (lane >= 20) return;
    bool okB = nB < NN;
    int cA = min(g_cnt[nA], CAP);
    int cB = okB ? min(g_cnt[nB], CAP) : 0;
    const int2* sltA = &g_slot[(long long)nA * CAP];
    const int2* sltB = &g_slot[(long long)nB * CAP];
    float2 aA = make_float2(0.f, 0.f), aB = make_float2(0.f, 0.f);
    int cmax = max(cA, cB);
    for (int kk = 0; kk < cmax; kk += 8) {
        if (kk < cA) gather_group<NC>(sltA, kk, cA, g_h2h, g_dinv, lane, aA);
        if (kk < cB) gather_group<NC>(sltB, kk, cB, g_h2h, g_dinv, lane, aB);
    }
    float b2x = __ldg(&b2[lane * 2]);
    float b2y = __ldg(&b2[lane * 2 + 1]);
    {
        float dc = g_dinv[nA];
        float2 self = __half22float2(*(const __half2*)&g_h2h[(long long)nA * NC + lane * 2]);
        float2 o;
        o.x = fmaf(dc, fmaf(dc, self.x, aA.x), b2x);
        o.y = fmaf(dc, fmaf(dc, self.y, aA.y), b2y);
        *(float2*)&out[(long long)nA * NC + lane * 2] = o;
    }
    if (okB) {
        float dc = g_dinv[nB];
        float2 self = __half22float2(*(const __half2*)&g_h2h[(long long)nB * NC + lane * 2]);
        float2 o;
        o.x = fmaf(dc, fmaf(dc, self.x, aB.x), b2x);
        o.y = fmaf(dc, fmaf(dc, self.y, aB.y), b2y);
        *(float2*)&out[(long long)nB * NC + lane * 2] = o;
    }
}

extern "C" void kernel_launch(void* const* d_in, const int* in_sizes, int n_in,
                              void* d_out, int out_size) {
    const float* x  = (const float*)d_in[0];
    const int*   ei = (const int*)d_in[1];     // int32 (JAX default x64-disabled)
    const float* ew = (const float*)d_in[2];
    const float* W1 = (const float*)d_in[3];
    const float* b1 = (const float*)d_in[4];
    const float* W2 = (const float*)d_in[5];
    const float* b2 = (const float*)d_in[6];
    float* out = (float*)d_out;

    (void)in_sizes; (void)n_in; (void)out_size;

    static cudaStream_t s2 = nullptr, s3 = nullptr;
    static cudaEvent_t eFork = nullptr, eJ2 = nullptr, eJ3 = nullptr;
    static int* cntPtr = nullptr;
    if (s2 == nullptr) {
        cudaStreamCreateWithFlags(&s2, cudaStreamNonBlocking);
        cudaStreamCreateWithFlags(&s3, cudaStreamNonBlocking);
        cudaEventCreateWithFlags(&eFork, cudaEventDisableTiming);
        cudaEventCreateWithFlags(&eJ2, cudaEventDisableTiming);
        cudaEventCreateWithFlags(&eJ3, cudaEventDisableTiming);
        cudaGetSymbolAddress((void**)&cntPtr, g_cnt);
    }

    // Fork from stream 0.
    cudaEventRecord(eFork, 0);
    cudaStreamWaitEvent(s2, eFork, 0);
    cudaStreamWaitEvent(s3, eFork, 0);

    // s2: dense layer-1 GEMM (independent of edges).
    gemm1<<<(NN + 63) / 64, 256, 0, s2>>>(x, W1);
    cudaEventRecord(eJ2, s2);

    // s3: slot placement (independent of degrees).
    cudaMemsetAsync(cntPtr, 0, NN * sizeof(int), s3);
    k_place_raw<<<(NE + 255) / 256, 256, 0, s3>>>(ei, ew);
    cudaEventRecord(eJ3, s3);

    // stream 0: degree chain.
    k_initdeg<<<(NN + 255) / 256, 256>>>();
    k_deg<<<(NE + 255) / 256, 256>>>(ei, ew);
    k_dinv<<<(NN + 255) / 256, 256>>>();

    // Join everything, then the fused tail.
    cudaStreamWaitEvent(0, eJ2, 0);
    cudaStreamWaitEvent(0, eJ3, 0);
    g1g2<<<(NN + 63) / 64, 256>>>(b1, W2);
    gather2<<<(NN / 2 + 7) / 8, 256>>>(b2, out);
}

// round 10
// speedup vs baseline: 1.0510x; 1.0510x over previous
#include <cuda_runtime.h>
#include <cuda_fp16.h>

#define NN 100000
#define NE 1600000
#define CAP 128
#define NF1 128
#define NH  64
#define NC  40

typedef unsigned long long ull;

// -------- scratch (device globals; no allocation allowed) --------
__device__ float  g_deg[NN];
__device__ float  g_dinv[NN];
__device__ int    g_cnt[NN];
__device__ int2   g_slot[(long long)NN * CAP];  // (src_row, w) then rescaled to (src_row, w*dinv[src])
__device__ __half g_h1h[(long long)NN * NH];    // fp16(x @ W1)
__device__ __half g_h2h[(long long)NN * NC];    // fp16(out1 @ W2)

// -------- packed f32x2 helpers --------
__device__ __forceinline__ ull pack2(float x, float y) {
    ull r;
    asm("mov.b64 %0, {%1, %2};" : "=l"(r) : "f"(x), "f"(y));
    return r;
}
__device__ __forceinline__ void fma2(ull& d, ull a, ull b) {
    asm("fma.rn.f32x2 %0, %1, %2, %0;" : "+l"(d) : "l"(a), "l"(b));
}
__device__ __forceinline__ float2 unpack2(ull v) {
    float2 f;
    asm("mov.b64 {%0, %1}, %2;" : "=f"(f.x), "=f"(f.y) : "l"(v));
    return f;
}

// -------- prep kernels --------
__global__ void k_initdeg() {
    int n = blockIdx.x * blockDim.x + threadIdx.x;
    if (n < NN) g_deg[n] = 1.0f;   // self-loop weight 1
}

__global__ void k_deg(const int* __restrict__ ei, const float* __restrict__ ew) {
    int e = blockIdx.x * blockDim.x + threadIdx.x;
    if (e < NE) {
        int c = ei[NE + e];
        if (c >= 0 && c < NN) atomicAdd(&g_deg[c], ew[e]);
    }
}

__global__ void k_dinv() {
    int n = blockIdx.x * blockDim.x + threadIdx.x;
    if (n < NN) {
        float d = g_deg[n];
        g_dinv[n] = d > 0.f ? rsqrtf(d) : 0.f;
    }
}

// Slot placement with RAW weight (no deg dependency) -> concurrent with degree chain.
__global__ void k_place_raw(const int* __restrict__ ei, const float* __restrict__ ew) {
    int e = blockIdx.x * blockDim.x + threadIdx.x;
    if (e >= NE) return;
    int r = ei[e];
    int c = ei[NE + e];
    if (r < 0 || r >= NN || c < 0 || c >= NN) return;
    int pos = atomicAdd(&g_cnt[c], 1);
    if (pos < CAP) {
        int2 s;
        s.x = r;
        s.y = __float_as_int(ew[e]);
        g_slot[(long long)c * CAP + pos] = s;
    }
}

// Fold dinv[src] into each slot weight (runs in the hidden prep window).
__global__ void k_rescale() {
    int node = blockIdx.x * 8 + (threadIdx.x >> 5);
    if (node >= NN) return;
    int lane = threadIdx.x & 31;
    int c = min(g_cnt[node], CAP);
    long long base = (long long)node * CAP;
    for (int k = lane; k < c; k += 32) {
        int2 s = g_slot[base + k];
        g_slot[base + k].y = __float_as_int(__int_as_float(s.y) * g_dinv[s.x]);
    }
}

// -------- one 8-slot masked gather group (pre-scaled pnorm, 12 loads) --------
template<int STRIDE>
__device__ __forceinline__ void gather_group(const int2* __restrict__ slots, int kk, int c,
                                             const __half* __restrict__ h,
                                             int lane, float2& acc) {
    int4 sa = *(const int4*)&slots[kk];
    int4 sb = *(const int4*)&slots[kk + 2];
    int4 sc = *(const int4*)&slots[kk + 4];
    int4 sd = *(const int4*)&slots[kk + 6];
    __half2 v0 = *(const __half2*)&h[(long long)sa.x * STRIDE + lane * 2];
    __half2 v1 = *(const __half2*)&h[(long long)sa.z * STRIDE + lane * 2];
    __half2 v2 = *(const __half2*)&h[(long long)sb.x * STRIDE + lane * 2];
    __half2 v3 = *(const __half2*)&h[(long long)sb.z * STRIDE + lane * 2];
    __half2 v4 = *(const __half2*)&h[(long long)sc.x * STRIDE + lane * 2];
    __half2 v5 = *(const __half2*)&h[(long long)sc.z * STRIDE + lane * 2];
    __half2 v6 = *(const __half2*)&h[(long long)sd.x * STRIDE + lane * 2];
    __half2 v7 = *(const __half2*)&h[(long long)sd.z * STRIDE + lane * 2];
    float n0 = (kk + 0 < c) ? __int_as_float(sa.y) : 0.f;
    float n1 = (kk + 1 < c) ? __int_as_float(sa.w) : 0.f;
    float n2 = (kk + 2 < c) ? __int_as_float(sb.y) : 0.f;
    float n3 = (kk + 3 < c) ? __int_as_float(sb.w) : 0.f;
    float n4 = (kk + 4 < c) ? __int_as_float(sc.y) : 0.f;
    float n5 = (kk + 5 < c) ? __int_as_float(sc.w) : 0.f;
    float n6 = (kk + 6 < c) ? __int_as_float(sd.y) : 0.f;
    float n7 = (kk + 7 < c) ? __int_as_float(sd.w) : 0.f;
    float2 f0 = __half22float2(v0), f1 = __half22float2(v1);
    float2 f2 = __half22float2(v2), f3 = __half22float2(v3);
    float2 f4 = __half22float2(v4), f5 = __half22float2(v5);
    float2 f6 = __half22float2(v6), f7 = __half22float2(v7);
    acc.x = fmaf(n0, f0.x, acc.x); acc.y = fmaf(n0, f0.y, acc.y);
    acc.x = fmaf(n1, f1.x, acc.x); acc.y = fmaf(n1, f1.y, acc.y);
    acc.x = fmaf(n2, f2.x, acc.x); acc.y = fmaf(n2, f2.y, acc.y);
    acc.x = fmaf(n3, f3.x, acc.x); acc.y = fmaf(n3, f3.y, acc.y);
    acc.x = fmaf(n4, f4.x, acc.x); acc.y = fmaf(n4, f4.y, acc.y);
    acc.x = fmaf(n5, f5.x, acc.x); acc.y = fmaf(n5, f5.y, acc.y);
    acc.x = fmaf(n6, f6.x, acc.x); acc.y = fmaf(n6, f6.y, acc.y);
    acc.x = fmaf(n7, f7.x, acc.x); acc.y = fmaf(n7, f7.y, acc.y);
}

// -------- GEMM1: g_h1h[N,64] = fp16(x[N,128] @ W1[128,64]) --------
__global__ void gemm1(const float* __restrict__ A, const float* __restrict__ B) {
    __shared__ __align__(16) float sA[64][68];
    __shared__ __align__(16) float sB[64][64];
    int tid = threadIdx.x;
    int tx = tid & 15, ty = tid >> 4;
    int row0 = blockIdx.x * 64;
    ull acc2[4][2] = {};

    for (int kc = 0; kc < 2; kc++) {
#pragma unroll
        for (int t = 0; t < 4; t++) {
            int lin = (t * 256 + tid) * 4;
            int r  = lin >> 6;
            int k0 = lin & 63;
            int grow = row0 + r;
            float4 v = make_float4(0.f, 0.f, 0.f, 0.f);
            if (grow < NN) v = *(const float4*)&A[(long long)grow * NF1 + kc * 64 + k0];
            *(float4*)&sA[r][k0] = v;
            float4 w = *(const float4*)&B[(kc * 64 + r) * NH + k0];
            *(float4*)&sB[r][k0] = w;
        }
        __syncthreads();
#pragma unroll
        for (int k = 0; k < 64; k++) {
            const ull* bp = (const ull*)&sB[k][tx * 4];
            ull b01 = bp[0];
            ull b23 = bp[1];
#pragma unroll
            for (int i = 0; i < 4; i++) {
                float a = sA[ty * 4 + i][k];
                ull pa = pack2(a, a);
                fma2(acc2[i][0], pa, b01);
                fma2(acc2[i][1], pa, b23);
            }
        }
        __syncthreads();
    }
#pragma unroll
    for (int i = 0; i < 4; i++) {
        int grow = row0 + ty * 4 + i;
        if (grow < NN) {
            __half2 h0 = __float22half2_rn(unpack2(acc2[i][0]));
            __half2 h1 = __float22half2_rn(unpack2(acc2[i][1]));
            uint2 st;
            st.x = *(unsigned*)&h0;
            st.y = *(unsigned*)&h1;
            *(uint2*)&g_h1h[(long long)grow * NH + tx * 4] = st;
        }
    }
}

// -------- FUSED gather1 + GEMM2, 2-node-interleaved gather (pre-scaled weights) --------
__global__ void g1g2(const float* __restrict__ b1, const float* __restrict__ W2) {
    __shared__ __align__(16) float sA[64][68];    // out1 rows (fp32)
    __shared__ __align__(16) float sB[64 * 40];   // W2
    int tid = threadIdx.x;          // 0..255
    int warp = tid >> 5, lane = tid & 31;
    int row0 = blockIdx.x * 64;

    for (int idx = tid; idx < 64 * 40; idx += 256) sB[idx] = W2[idx];

    float bx = __ldg(&b1[lane * 2]);
    float by = __ldg(&b1[lane * 2 + 1]);

#pragma unroll
    for (int p = 0; p < 4; p++) {
        int rA = warp * 8 + p * 2;
        int nA = row0 + rA;
        int nB = nA + 1;
        bool okA = nA < NN, okB = nB < NN;
        float2 aA = make_float2(0.f, 0.f), aB = make_float2(0.f, 0.f);
        int cA = okA ? min(g_cnt[nA], CAP) : 0;
        int cB = okB ? min(g_cnt[nB], CAP) : 0;
        const int2* sltA = &g_slot[(long long)nA * CAP];
        const int2* sltB = &g_slot[(long long)nB * CAP];
        int cmax = max(cA, cB);
        for (int kk = 0; kk < cmax; kk += 8) {
            if (kk < cA) gather_group<NH>(sltA, kk, cA, g_h1h, lane, aA);
            if (kk < cB) gather_group<NH>(sltB, kk, cB, g_h1h, lane, aB);
        }
        float2 oA = make_float2(0.f, 0.f), oB = make_float2(0.f, 0.f);
        if (okA) {
            float dc = g_dinv[nA];
            float2 self = __half22float2(*(const __half2*)&g_h1h[(long long)nA * NH + lane * 2]);
            oA.x = fmaxf(fmaf(dc, fmaf(dc, self.x, aA.x), bx), 0.f);
            oA.y = fmaxf(fmaf(dc, fmaf(dc, self.y, aA.y), by), 0.f);
        }
        if (okB) {
            float dc = g_dinv[nB];
            float2 self = __half22float2(*(const __half2*)&g_h1h[(long long)nB * NH + lane * 2]);
            oB.x = fmaxf(fmaf(dc, fmaf(dc, self.x, aB.x), bx), 0.f);
            oB.y = fmaxf(fmaf(dc, fmaf(dc, self.y, aB.y), by), 0.f);
        }
        *(float2*)&sA[rA][lane * 2] = oA;
        *(float2*)&sA[rA + 1][lane * 2] = oB;
    }
    __syncthreads();

    if (tid < 160) {
        int tx = tid % 10, ty = tid / 10;
        ull acc2[4][2] = {};
#pragma unroll
        for (int k = 0; k < 64; k++) {
            const ull* bp = (const ull*)&sB[k * 40 + tx * 4];
            ull b01 = bp[0];
            ull b23 = bp[1];
#pragma unroll
            for (int i = 0; i < 4; i++) {
                float a = sA[ty * 4 + i][k];
                ull pa = pack2(a, a);
                fma2(acc2[i][0], pa, b01);
                fma2(acc2[i][1], pa, b23);
            }
        }
#pragma unroll
        for (int i = 0; i < 4; i++) {
            int grow = row0 + ty * 4 + i;
            if (grow < NN) {
                __half2 h0 = __float22half2_rn(unpack2(acc2[i][0]));
                __half2 h1 = __float22half2_rn(unpack2(acc2[i][1]));
                uint2 st;
                st.x = *(unsigned*)&h0;
                st.y = *(unsigned*)&h1;
                *(uint2*)&g_h2h[(long long)grow * NC + tx * 4] = st;
            }
        }
    }
}

// -------- gather layer 2: warp per 2 nodes, lanes 0..19 (pre-scaled weights) --------
__global__ void gather2(const float* __restrict__ b2, float* __restrict__ out) {
    int warp = blockIdx.x * 8 + (threadIdx.x >> 5);
    int nA = warp * 2;
    int nB = nA + 1;
    if (nA >= NN) return;
    int lane = threadIdx.x & 31;
    if (lane >= 20) return;
    bool okB = nB < NN;
    int cA = min(g_cnt[nA], CAP);
    int cB = okB ? min(g_cnt[nB], CAP) : 0;
    const int2* sltA = &g_slot[(long long)nA * CAP];
    const int2* sltB = &g_slot[(long long)nB * CAP];
    float2 aA = make_float2(0.f, 0.f), aB = make_float2(0.f, 0.f);
    int cmax = max(cA, cB);
    for (int kk = 0; kk < cmax; kk += 8) {
        if (kk < cA) gather_group<NC>(sltA, kk, cA, g_h2h, lane, aA);
        if (kk < cB) gather_group<NC>(sltB, kk, cB, g_h2h, lane, aB);
    }
    float b2x = __ldg(&b2[lane * 2]);
    float b2y = __ldg(&b2[lane * 2 + 1]);
    {
        float dc = g_dinv[nA];
        float2 self = __half22float2(*(const __half2*)&g_h2h[(long long)nA * NC + lane * 2]);
        float2 o;
        o.x = fmaf(dc, fmaf(dc, self.x, aA.x), b2x);
        o.y = fmaf(dc, fmaf(dc, self.y, aA.y), b2y);
        *(float2*)&out[(long long)nA * NC + lane * 2] = o;
    }
    if (okB) {
        float dc = g_dinv[nB];
        float2 self = __half22float2(*(const __half2*)&g_h2h[(long long)nB * NC + lane * 2]);
        float2 o;
        o.x = fmaf(dc, fmaf(dc, self.x, aB.x), b2x);
        o.y = fmaf(dc, fmaf(dc, self.y, aB.y), b2y);
        *(float2*)&out[(long long)nB * NC + lane * 2] = o;
    }
}

extern "C" void kernel_launch(void* const* d_in, const int* in_sizes, int n_in,
                              void* d_out, int out_size) {
    const float* x  = (const float*)d_in[0];
    const int*   ei = (const int*)d_in[1];     // int32 (JAX default x64-disabled)
    const float* ew = (const float*)d_in[2];
    const float* W1 = (const float*)d_in[3];
    const float* b1 = (const float*)d_in[4];
    const float* W2 = (const float*)d_in[5];
    const float* b2 = (const float*)d_in[6];
    float* out = (float*)d_out;

    (void)in_sizes; (void)n_in; (void)out_size;

    static cudaStream_t s2 = nullptr, s3 = nullptr;
    static cudaEvent_t eFork = nullptr, eJ2 = nullptr, eJ3 = nullptr;
    static int* cntPtr = nullptr;
    if (s2 == nullptr) {
        cudaStreamCreateWithFlags(&s2, cudaStreamNonBlocking);
        cudaStreamCreateWithFlags(&s3, cudaStreamNonBlocking);
        cudaEventCreateWithFlags(&eFork, cudaEventDisableTiming);
        cudaEventCreateWithFlags(&eJ2, cudaEventDisableTiming);
        cudaEventCreateWithFlags(&eJ3, cudaEventDisableTiming);
        cudaGetSymbolAddress((void**)&cntPtr, g_cnt);
    }

    // Fork from stream 0.
    cudaEventRecord(eFork, 0);
    cudaStreamWaitEvent(s2, eFork, 0);
    cudaStreamWaitEvent(s3, eFork, 0);

    // s2: dense layer-1 GEMM (independent of edges) — hides the whole prep window.
    gemm1<<<(NN + 63) / 64, 256, 0, s2>>>(x, W1);
    cudaEventRecord(eJ2, s2);

    // s3: slot placement with raw weights (independent of degrees).
    cudaMemsetAsync(cntPtr, 0, NN * sizeof(int), s3);
    k_place_raw<<<(NE + 255) / 256, 256, 0, s3>>>(ei, ew);
    cudaEventRecord(eJ3, s3);

    // stream 0: degree chain, then fold dinv into slot weights (off the tail).
    k_initdeg<<<(NN + 255) / 256, 256>>>();
    k_deg<<<(NE + 255) / 256, 256>>>(ei, ew);
    k_dinv<<<(NN + 255) / 256, 256>>>();
    cudaStreamWaitEvent(0, eJ3, 0);
    k_rescale<<<(NN + 7) / 8, 256>>>();

    // Join gemm1, then the fused tail.
    cudaStreamWaitEvent(0, eJ2, 0);
    g1g2<<<(NN + 63) / 64, 256>>>(b1, W2);
    gather2<<<(NN / 2 + 7) / 8, 256>>>(b2, out);
}

// round 11
// speedup vs baseline: 1.1011x; 1.0477x over previous
#include <cuda_runtime.h>
#include <cuda_fp16.h>

#define NN 100000
#define NE 1600000
#define CAP 128
#define NF1 128
#define NH  64
#define NC  40

typedef unsigned long long ull;

// -------- scratch (device globals; no allocation allowed) --------
__device__ float  g_deg[NN];
__device__ int    g_cnt[NN];
__device__ int2   g_slot[(long long)NN * CAP];  // (src_row, float_bits(dinv[src]*w)); zero-init -> row 0 safe
__device__ __half g_h1h[(long long)NN * NH];    // fp16(x @ W1)
__device__ __half g_h2h[(long long)NN * NC];    // fp16(out1 @ W2)

// -------- packed f32x2 helpers --------
__device__ __forceinline__ ull pack2(float x, float y) {
    ull r;
    asm("mov.b64 %0, {%1, %2};" : "=l"(r) : "f"(x), "f"(y));
    return r;
}
__device__ __forceinline__ void fma2(ull& d, ull a, ull b) {
    asm("fma.rn.f32x2 %0, %1, %2, %0;" : "+l"(d) : "l"(a), "l"(b));
}
__device__ __forceinline__ float2 unpack2(ull v) {
    float2 f;
    asm("mov.b64 {%0, %1}, %2;" : "=f"(f.x), "=f"(f.y) : "l"(v));
    return f;
}

// -------- prep kernels (R8 serial form) --------
__global__ void k_init() {
    int n = blockIdx.x * blockDim.x + threadIdx.x;
    if (n < NN) { g_deg[n] = 1.0f; g_cnt[n] = 0; }  // self-loop weight 1
}

__global__ void k_deg(const int* __restrict__ ei, const float* __restrict__ ew) {
    int e = blockIdx.x * blockDim.x + threadIdx.x;
    if (e < NE) {
        int c = ei[NE + e];
        if (c >= 0 && c < NN) atomicAdd(&g_deg[c], ew[e]);
    }
}

__global__ void k_place(const int* __restrict__ ei, const float* __restrict__ ew) {
    int e = blockIdx.x * blockDim.x + threadIdx.x;
    if (e >= NE) return;
    int r = ei[e];
    int c = ei[NE + e];
    if (r < 0 || r >= NN || c < 0 || c >= NN) return;
    float dr = rsqrtf(g_deg[r]);          // deg >= 1 always (self loop)
    float pnorm = dr * ew[e];             // dinv[c] factored out; applied in gather epilogue
    int pos = atomicAdd(&g_cnt[c], 1);
    if (pos < CAP) {
        int2 s;
        s.x = r;
        s.y = __float_as_int(pnorm);
        g_slot[(long long)c * CAP + pos] = s;
    }
}

// -------- one 8-slot masked gather group (pre-scaled pnorm, 12 loads) --------
template<int STRIDE>
__device__ __forceinline__ void gather_group(const int2* __restrict__ slots, int kk, int c,
                                             const __half* __restrict__ h,
                                             int lane, float2& acc) {
    int4 sa = *(const int4*)&slots[kk];
    int4 sb = *(const int4*)&slots[kk + 2];
    int4 sc = *(const int4*)&slots[kk + 4];
    int4 sd = *(const int4*)&slots[kk + 6];
    __half2 v0 = *(const __half2*)&h[(long long)sa.x * STRIDE + lane * 2];
    __half2 v1 = *(const __half2*)&h[(long long)sa.z * STRIDE + lane * 2];
    __half2 v2 = *(const __half2*)&h[(long long)sb.x * STRIDE + lane * 2];
    __half2 v3 = *(const __half2*)&h[(long long)sb.z * STRIDE + lane * 2];
    __half2 v4 = *(const __half2*)&h[(long long)sc.x * STRIDE + lane * 2];
    __half2 v5 = *(const __half2*)&h[(long long)sc.z * STRIDE + lane * 2];
    __half2 v6 = *(const __half2*)&h[(long long)sd.x * STRIDE + lane * 2];
    __half2 v7 = *(const __half2*)&h[(long long)sd.z * STRIDE + lane * 2];
    float n0 = (kk + 0 < c) ? __int_as_float(sa.y) : 0.f;
    float n1 = (kk + 1 < c) ? __int_as_float(sa.w) : 0.f;
    float n2 = (kk + 2 < c) ? __int_as_float(sb.y) : 0.f;
    float n3 = (kk + 3 < c) ? __int_as_float(sb.w) : 0.f;
    float n4 = (kk + 4 < c) ? __int_as_float(sc.y) : 0.f;
    float n5 = (kk + 5 < c) ? __int_as_float(sc.w) : 0.f;
    float n6 = (kk + 6 < c) ? __int_as_float(sd.y) : 0.f;
    float n7 = (kk + 7 < c) ? __int_as_float(sd.w) : 0.f;
    float2 f0 = __half22float2(v0), f1 = __half22float2(v1);
    float2 f2 = __half22float2(v2), f3 = __half22float2(v3);
    float2 f4 = __half22float2(v4), f5 = __half22float2(v5);
    float2 f6 = __half22float2(v6), f7 = __half22float2(v7);
    acc.x = fmaf(n0, f0.x, acc.x); acc.y = fmaf(n0, f0.y, acc.y);
    acc.x = fmaf(n1, f1.x, acc.x); acc.y = fmaf(n1, f1.y, acc.y);
    acc.x = fmaf(n2, f2.x, acc.x); acc.y = fmaf(n2, f2.y, acc.y);
    acc.x = fmaf(n3, f3.x, acc.x); acc.y = fmaf(n3, f3.y, acc.y);
    acc.x = fmaf(n4, f4.x, acc.x); acc.y = fmaf(n4, f4.y, acc.y);
    acc.x = fmaf(n5, f5.x, acc.x); acc.y = fmaf(n5, f5.y, acc.y);
    acc.x = fmaf(n6, f6.x, acc.x); acc.y = fmaf(n6, f6.y, acc.y);
    acc.x = fmaf(n7, f7.x, acc.x); acc.y = fmaf(n7, f7.y, acc.y);
}

// -------- GEMM1: g_h1h[N,64] = fp16(x[N,128] @ W1[128,64]) --------
__global__ void gemm1(const float* __restrict__ A, const float* __restrict__ B) {
    __shared__ __align__(16) float sA[64][68];
    __shared__ __align__(16) float sB[64][64];
    int tid = threadIdx.x;
    int tx = tid & 15, ty = tid >> 4;
    int row0 = blockIdx.x * 64;
    ull acc2[4][2] = {};

    for (int kc = 0; kc < 2; kc++) {
#pragma unroll
        for (int t = 0; t < 4; t++) {
            int lin = (t * 256 + tid) * 4;
            int r  = lin >> 6;
            int k0 = lin & 63;
            int grow = row0 + r;
            float4 v = make_float4(0.f, 0.f, 0.f, 0.f);
            if (grow < NN) v = *(const float4*)&A[(long long)grow * NF1 + kc * 64 + k0];
            *(float4*)&sA[r][k0] = v;
            float4 w = *(const float4*)&B[(kc * 64 + r) * NH + k0];
            *(float4*)&sB[r][k0] = w;
        }
        __syncthreads();
#pragma unroll
        for (int k = 0; k < 64; k++) {
            const ull* bp = (const ull*)&sB[k][tx * 4];
            ull b01 = bp[0];
            ull b23 = bp[1];
#pragma unroll
            for (int i = 0; i < 4; i++) {
                float a = sA[ty * 4 + i][k];
                ull pa = pack2(a, a);
                fma2(acc2[i][0], pa, b01);
                fma2(acc2[i][1], pa, b23);
            }
        }
        __syncthreads();
    }
#pragma unroll
    for (int i = 0; i < 4; i++) {
        int grow = row0 + ty * 4 + i;
        if (grow < NN) {
            __half2 h0 = __float22half2_rn(unpack2(acc2[i][0]));
            __half2 h1 = __float22half2_rn(unpack2(acc2[i][1]));
            uint2 st;
            st.x = *(unsigned*)&h0;
            st.y = *(unsigned*)&h1;
            *(uint2*)&g_h1h[(long long)grow * NH + tx * 4] = st;
        }
    }
}

// -------- FUSED gather1 + GEMM2, 2-node-interleaved gather --------
__global__ void g1g2(const float* __restrict__ b1, const float* __restrict__ W2) {
    __shared__ __align__(16) float sA[64][68];    // out1 rows (fp32)
    __shared__ __align__(16) float sB[64 * 40];   // W2
    int tid = threadIdx.x;          // 0..255
    int warp = tid >> 5, lane = tid & 31;
    int row0 = blockIdx.x * 64;

    for (int idx = tid; idx < 64 * 40; idx += 256) sB[idx] = W2[idx];

    float bx = __ldg(&b1[lane * 2]);
    float by = __ldg(&b1[lane * 2 + 1]);

#pragma unroll
    for (int p = 0; p < 4; p++) {
        int rA = warp * 8 + p * 2;
        int nA = row0 + rA;
        int nB = nA + 1;
        bool okA = nA < NN, okB = nB < NN;
        float2 aA = make_float2(0.f, 0.f), aB = make_float2(0.f, 0.f);
        int cA = okA ? min(g_cnt[nA], CAP) : 0;
        int cB = okB ? min(g_cnt[nB], CAP) : 0;
        const int2* sltA = &g_slot[(long long)nA * CAP];
        const int2* sltB = &g_slot[(long long)nB * CAP];
        int cmax = max(cA, cB);
        for (int kk = 0; kk < cmax; kk += 8) {
            if (kk < cA) gather_group<NH>(sltA, kk, cA, g_h1h, lane, aA);
            if (kk < cB) gather_group<NH>(sltB, kk, cB, g_h1h, lane, aB);
        }
        float2 oA = make_float2(0.f, 0.f), oB = make_float2(0.f, 0.f);
        if (okA) {
            float dc = rsqrtf(g_deg[nA]);
            float2 self = __half22float2(*(const __half2*)&g_h1h[(long long)nA * NH + lane * 2]);
            oA.x = fmaxf(fmaf(dc, fmaf(dc, self.x, aA.x), bx), 0.f);
            oA.y = fmaxf(fmaf(dc, fmaf(dc, self.y, aA.y), by), 0.f);
        }
        if (okB) {
            float dc = rsqrtf(g_deg[nB]);
            float2 self = __half22float2(*(const __half2*)&g_h1h[(long long)nB * NH + lane * 2]);
            oB.x = fmaxf(fmaf(dc, fmaf(dc, self.x, aB.x), bx), 0.f);
            oB.y = fmaxf(fmaf(dc, fmaf(dc, self.y, aB.y), by), 0.f);
        }
        *(float2*)&sA[rA][lane * 2] = oA;
        *(float2*)&sA[rA + 1][lane * 2] = oB;
    }
    __syncthreads();

    if (tid < 160) {
        int tx = tid % 10, ty = tid / 10;
        ull acc2[4][2] = {};
#pragma unroll
        for (int k = 0; k < 64; k++) {
            const ull* bp = (const ull*)&sB[k * 40 + tx * 4];
            ull b01 = bp[0];
            ull b23 = bp[1];
#pragma unroll
            for (int i = 0; i < 4; i++) {
                float a = sA[ty * 4 + i][k];
                ull pa = pack2(a, a);
                fma2(acc2[i][0], pa, b01);
                fma2(acc2[i][1], pa, b23);
            }
        }
#pragma unroll
        for (int i = 0; i < 4; i++) {
            int grow = row0 + ty * 4 + i;
            if (grow < NN) {
                __half2 h0 = __float22half2_rn(unpack2(acc2[i][0]));
                __half2 h1 = __float22half2_rn(unpack2(acc2[i][1]));
                uint2 st;
                st.x = *(unsigned*)&h0;
                st.y = *(unsigned*)&h1;
                *(uint2*)&g_h2h[(long long)grow * NC + tx * 4] = st;
            }
        }
    }
}

// -------- gather layer 2: warp per 2 nodes, lanes 0..19 --------
__global__ void gather2(const float* __restrict__ b2, float* __restrict__ out) {
    int warp = blockIdx.x * 8 + (threadIdx.x >> 5);
    int nA = warp * 2;
    int nB = nA + 1;
    if (nA >= NN) return;
    int lane = threadIdx.x & 31;
    if (lane >= 20) return;
    bool okB = nB < NN;
    int cA = min(g_cnt[nA], CAP);
    int cB = okB ? min(g_cnt[nB], CAP) : 0;
    const int2* sltA = &g_slot[(long long)nA * CAP];
    const int2* sltB = &g_slot[(long long)nB * CAP];
    float2 aA = make_float2(0.f, 0.f), aB = make_float2(0.f, 0.f);
    int cmax = max(cA, cB);
    for (int kk = 0; kk < cmax; kk += 8) {
        if (kk < cA) gather_group<NC>(sltA, kk, cA, g_h2h, lane, aA);
        if (kk < cB) gather_group<NC>(sltB, kk, cB, g_h2h, lane, aB);
    }
    float b2x = __ldg(&b2[lane * 2]);
    float b2y = __ldg(&b2[lane * 2 + 1]);
    {
        float dc = rsqrtf(g_deg[nA]);
        float2 self = __half22float2(*(const __half2*)&g_h2h[(long long)nA * NC + lane * 2]);
        float2 o;
        o.x = fmaf(dc, fmaf(dc, self.x, aA.x), b2x);
        o.y = fmaf(dc, fmaf(dc, self.y, aA.y), b2y);
        *(float2*)&out[(long long)nA * NC + lane * 2] = o;
    }
    if (okB) {
        float dc = rsqrtf(g_deg[nB]);
        float2 self = __half22float2(*(const __half2*)&g_h2h[(long long)nB * NC + lane * 2]);
        float2 o;
        o.x = fmaf(dc, fmaf(dc, self.x, aB.x), b2x);
        o.y = fmaf(dc, fmaf(dc, self.y, aB.y), b2y);
        *(float2*)&out[(long long)nB * NC + lane * 2] = o;
    }
}

extern "C" void kernel_launch(void* const* d_in, const int* in_sizes, int n_in,
                              void* d_out, int out_size) {
    const float* x  = (const float*)d_in[0];
    const int*   ei = (const int*)d_in[1];     // int32 (JAX default x64-disabled)
    const float* ew = (const float*)d_in[2];
    const float* W1 = (const float*)d_in[3];
    const float* b1 = (const float*)d_in[4];
    const float* W2 = (const float*)d_in[5];
    const float* b2 = (const float*)d_in[6];
    float* out = (float*)d_out;

    (void)in_sizes; (void)n_in; (void)out_size;

    static cudaStream_t s2 = nullptr;
    static cudaEvent_t eFork = nullptr, eJoin = nullptr;
    if (s2 == nullptr) {
        cudaStreamCreateWithFlags(&s2, cudaStreamNonBlocking);
        cudaEventCreateWithFlags(&eFork, cudaEventDisableTiming);
        cudaEventCreateWithFlags(&eJoin, cudaEventDisableTiming);
    }

    // Fork: gemm1 (x,W1 only) runs concurrently with edge preprocessing.
    cudaEventRecord(eFork, 0);
    cudaStreamWaitEvent(s2, eFork, 0);
    gemm1<<<(NN + 63) / 64, 256, 0, s2>>>(x, W1);
    cudaEventRecord(eJoin, s2);

    // stream 0: serial prep (R8 form — fully hidden under gemm1).
    k_init<<<(NN + 255) / 256, 256>>>();
    k_deg<<<(NE + 255) / 256, 256>>>(ei, ew);
    k_place<<<(NE + 255) / 256, 256>>>(ei, ew);

    // Join, then the fused tail.
    cudaStreamWaitEvent(0, eJoin, 0);
    g1g2<<<(NN + 63) / 64, 256>>>(b1, W2);
    gather2<<<(NN / 2 + 7) / 8, 256>>>(b2, out);
}